// round 10
// baseline (speedup 1.0000x reference)
#include <cuda_runtime.h>
#include <cuda_bf16.h>
#include <stdint.h>

#define BB 8
#define NN 4096
#define CC 64
#define QD 8
#define BM 64          // query rows per block
#define BN 64          // key tile rows
#define QT (NN / BM)
#define KT (NN / BN)
#define LDHB 80        // fp8 H smem: bytes per channel column (bank-spread)
#define LDO 72         // epilogue O overlay leading dim (floats)
#define LOG2E 1.4426950408889634f

// Static device scratch for projections.
__device__ __nv_bfloat16 g_f[BB * NN * QD];   // 0.5 MB
__device__ __nv_bfloat16 g_g[BB * NN * QD];   // 0.5 MB (pre-scaled by log2e)
__device__ uint8_t       g_ht[BB * CC * NN];  // 2 MB: h transposed, e4m3 [b][c][n]

// ---------------------------------------------------------------------------
// PTX helpers
// ---------------------------------------------------------------------------
__device__ __forceinline__ void mma_16n8k8(float* c, const uint32_t* a, uint32_t b)
{
    asm volatile(
        "mma.sync.aligned.m16n8k8.row.col.f32.bf16.bf16.f32 "
        "{%0,%1,%2,%3}, {%4,%5}, {%6}, {%0,%1,%2,%3};\n"
        : "+f"(c[0]), "+f"(c[1]), "+f"(c[2]), "+f"(c[3])
        : "r"(a[0]), "r"(a[1]), "r"(b));
}

__device__ __forceinline__ void mma_16n8k16(float* c, const uint32_t* a, const uint32_t* b)
{
    asm volatile(
        "mma.sync.aligned.m16n8k16.row.col.f32.bf16.bf16.f32 "
        "{%0,%1,%2,%3}, {%4,%5,%6,%7}, {%8,%9}, {%0,%1,%2,%3};\n"
        : "+f"(c[0]), "+f"(c[1]), "+f"(c[2]), "+f"(c[3])
        : "r"(a[0]), "r"(a[1]), "r"(a[2]), "r"(a[3]), "r"(b[0]), "r"(b[1]));
}

// FP8 e4m3 MMA, k=32 (2x MACs per instruction vs bf16 k16).
__device__ __forceinline__ void mma_e4m3(float* c, const uint32_t* a,
                                         uint32_t b0, uint32_t b1)
{
    asm volatile(
        "mma.sync.aligned.m16n8k32.row.col.f32.e4m3.e4m3.f32 "
        "{%0,%1,%2,%3}, {%4,%5,%6,%7}, {%8,%9}, {%0,%1,%2,%3};\n"
        : "+f"(c[0]), "+f"(c[1]), "+f"(c[2]), "+f"(c[3])
        : "r"(a[0]), "r"(a[1]), "r"(a[2]), "r"(a[3]), "r"(b0), "r"(b1));
}

__device__ __forceinline__ void ldsm_x4(uint32_t* r, const void* smem_ptr)
{
    uint32_t addr = (uint32_t)__cvta_generic_to_shared(smem_ptr);
    asm volatile(
        "ldmatrix.sync.aligned.m8n8.x4.shared.b16 {%0,%1,%2,%3}, [%4];\n"
        : "=r"(r[0]), "=r"(r[1]), "=r"(r[2]), "=r"(r[3]) : "r"(addr));
}

__device__ __forceinline__ void ldsm_x4_trans(uint32_t* r, const void* smem_ptr)
{
    uint32_t addr = (uint32_t)__cvta_generic_to_shared(smem_ptr);
    asm volatile(
        "ldmatrix.sync.aligned.m8n8.x4.trans.shared.b16 {%0,%1,%2,%3}, [%4];\n"
        : "=r"(r[0]), "=r"(r[1]), "=r"(r[2]), "=r"(r[3]) : "r"(addr));
}

__device__ __forceinline__ uint32_t pack_bf162(float a, float b)
{
    __nv_bfloat162 t = __floats2bfloat162_rn(a, b);
    return *(uint32_t*)&t;
}

// (lo, hi) f32 -> f16x2 -> exp2 both (one MUFU) -> e4m3x2 (b0=exp2(lo), b1=exp2(hi)).
__device__ __forceinline__ uint16_t pk8(float lo, float hi)
{
    uint32_t t;
    asm("cvt.rn.f16x2.f32 %0, %1, %2;\n" : "=r"(t) : "f"(hi), "f"(lo));
    asm("ex2.approx.f16x2 %0, %0;\n" : "+r"(t));
    uint16_t r;
    asm("cvt.rn.satfinite.e4m3x2.f16x2 %0, %1;\n" : "=h"(r) : "r"(t));
    return r;
}

// single f32 -> e4m3 byte
__device__ __forceinline__ uint8_t f2e4m3(float v)
{
    uint16_t r;
    asm("cvt.rn.satfinite.e4m3x2.f32 %0, %1, %2;\n" : "=h"(r) : "f"(0.f), "f"(v));
    return (uint8_t)r;
}

__device__ __forceinline__ uint32_t prmt(uint32_t a, uint32_t b, uint32_t ctl)
{
    uint32_t d;
    asm("prmt.b32 %0, %1, %2, %3;\n" : "=r"(d) : "r"(a), "r"(b), "r"(ctl));
    return d;
}

__device__ __forceinline__ void cp_async16(void* smem_dst, const void* gmem_src)
{
    uint32_t d = (uint32_t)__cvta_generic_to_shared(smem_dst);
    asm volatile("cp.async.cg.shared.global [%0], [%1], 16;\n"
                 :: "r"(d), "l"(gmem_src) : "memory");
}
__device__ __forceinline__ void cp_async_commit()
{ asm volatile("cp.async.commit_group;\n" ::: "memory"); }
__device__ __forceinline__ void cp_async_wait0()
{ asm volatile("cp.async.wait_group 0;\n" ::: "memory"); }

// ---------------------------------------------------------------------------
// Kernel 1: projections as HMMA GEMM.  [128 rows x 64] @ [64 x 80] per block.
// f, g row-major bf16 (g pre-scaled by log2e); h TRANSPOSED e4m3 (g_ht).
// ---------------------------------------------------------------------------
#define LDW 88
#define LDX 72
__global__ __launch_bounds__(256) void proj_kernel(
    const float* __restrict__ x,
    const float* __restrict__ kf,
    const float* __restrict__ kg,
    const float* __restrict__ kh)
{
    __shared__ __nv_bfloat16 sW[64 * LDW];
    __shared__ __nv_bfloat16 sX[128 * LDX];

    int tid  = threadIdx.x;
    int lane = tid & 31;
    int w    = tid >> 5;
    int gid  = lane >> 2;
    int tg   = lane & 3;

    for (int idx = tid; idx < 64 * 80; idx += 256) {
        int c = idx / 80, d = idx % 80;
        float v;
        if (d < 8)       v = kf[c * 8 + d];
        else if (d < 16) v = kg[c * 8 + (d - 8)] * LOG2E;
        else             v = kh[c * 64 + (d - 16)];
        sW[c * LDW + d] = __float2bfloat16(v);
    }
    long base = (long)blockIdx.x * 128;
    const float4* xg = (const float4*)(x + base * 64);
    for (int i = tid; i < 2048; i += 256) {
        int r = i >> 4, c4 = (i & 15) * 4;
        float4 v = xg[i];
        __nv_bfloat162* dst = (__nv_bfloat162*)&sX[r * LDX + c4];
        dst[0] = __floats2bfloat162_rn(v.x, v.y);
        dst[1] = __floats2bfloat162_rn(v.z, v.w);
    }
    __syncthreads();

    float c[10][4];
#pragma unroll
    for (int n = 0; n < 10; n++)
#pragma unroll
        for (int i = 0; i < 4; i++) c[n][i] = 0.f;

#pragma unroll
    for (int kk = 0; kk < 4; kk++) {
        uint32_t a[4];
        ldsm_x4(a, &sX[(w * 16 + (lane & 15)) * LDX + kk * 16 + (lane >> 4) * 8]);
#pragma unroll
        for (int np = 0; np < 5; np++) {
            uint32_t bfr[4];
            ldsm_x4_trans(bfr,
                &sW[(kk * 16 + (lane & 15)) * LDW + np * 16 + (lane >> 4) * 8]);
            mma_16n8k16(c[2 * np],     a, &bfr[0]);
            mma_16n8k16(c[2 * np + 1], a, &bfr[2]);
        }
    }

    long r0 = base + w * 16 + gid;
    long r1 = r0 + 8;
    int  bb = (int)(r0 >> 12);
    int  n0 = (int)(r0 & 4095);
    int  n1 = n0 + 8;
    long cb = (long)bb * CC;
#pragma unroll
    for (int np = 0; np < 5; np++) {
#pragma unroll
        for (int h = 0; h < 2; h++) {
            int dbase = 16 * np + 8 * h;
            if (dbase == 0) {
                *(uint32_t*)&g_f[r0 * QD + 2 * tg] = pack_bf162(c[0][0], c[0][1]);
                *(uint32_t*)&g_f[r1 * QD + 2 * tg] = pack_bf162(c[0][2], c[0][3]);
            } else if (dbase == 8) {
                *(uint32_t*)&g_g[r0 * QD + 2 * tg] = pack_bf162(c[1][0], c[1][1]);
                *(uint32_t*)&g_g[r1 * QD + 2 * tg] = pack_bf162(c[1][2], c[1][3]);
            } else {
                int d = dbase - 16 + 2 * tg;
                g_ht[(cb + d)     * NN + n0] = f2e4m3(c[2 * np + h][0]);
                g_ht[(cb + d + 1) * NN + n0] = f2e4m3(c[2 * np + h][1]);
                g_ht[(cb + d)     * NN + n1] = f2e4m3(c[2 * np + h][2]);
                g_ht[(cb + d + 1) * NN + n1] = f2e4m3(c[2 * np + h][3]);
            }
        }
    }
}

// ---------------------------------------------------------------------------
// Kernel 2: flash attention, FP8 PV. 128 threads = 2 key-parity pairs x 2
// warps; warp owns 32 rows (2 m16 chunks). S = G@F^T in bf16 k8; P converted
// to e4m3 in registers (f16x2 ex2), k32 A-fragments assembled via shfl+prmt;
// PV and rowsum on m16n8k32 e4m3 MMA (2x MACs/instr). H is fp8 channel-major
// in smem, B-fragments are conflict-free LDS.32 shared across both chunks.
// ---------------------------------------------------------------------------
__global__ __launch_bounds__(128) void attn_kernel(
    const float* __restrict__ x,
    const float* __restrict__ gamma_p,
    float* __restrict__ out)
{
    __shared__ __nv_bfloat16 sG[BM * QD];              // 1 KB
    __shared__ __nv_bfloat16 sF[2][2][BN * QD];        // 4 KB  [pair][buf]
    __shared__ uint8_t       sH[2][2][CC * LDHB];      // 20 KB [pair][buf]: [chan][key]
    __shared__ float         sL[BM];

    int tid  = threadIdx.x;
    int lane = tid & 31;
    int w    = tid >> 5;          // 0..3
    int pair = w >> 1;            // key-tile parity this warp handles
    int wp   = w & 1;             // warp-in-pair: row half
    int pt   = tid & 63;          // pair-local thread id
    int gid  = lane >> 2;
    int tg   = lane & 3;
    int b    = blockIdx.x / QT;
    int qt   = blockIdx.x % QT;
    long qbase = (long)b * NN + (long)qt * BM;
    long kb0   = (long)b * NN;
    long hbase = (long)b * CC * NN;

    float gmm = gamma_p[0];

    const uint32_t BONES = 0x38383838u;         // 1.0 e4m3 x4
    int      L0  = (lane & 28) | (2 * (tg & 1));
    int      L1  = L0 + 1;
    uint32_t ctl = (tg < 2) ? 0x5410u : 0x7632u;

    // Prologue: G tile + each pair's first key tile (kt = pair).
    if (tid < 64) cp_async16(&sG[tid * 8], &g_g[(qbase + tid) * QD]);
    {
        long kb = kb0 + (long)pair * BN;
        cp_async16(&sF[pair][0][pt * 8], &g_f[(kb + pt) * QD]);
#pragma unroll
        for (int i = 0; i < 4; i++) {
            int idx = pt + 64 * i;               // 0..255
            int col = idx >> 2, seg = idx & 3;
            cp_async16(&sH[pair][0][col * LDHB + seg * 16],
                       &g_ht[hbase + (long)col * NN + (long)pair * BN + seg * 16]);
        }
    }
    cp_async_commit();
    cp_async_wait0();
    __syncthreads();

    // G A-fragments for rows wp*32 + {gid, gid+8, gid+16, gid+24}.
    uint32_t ga0[2], ga1[2];
    ga0[0] = *(const uint32_t*)&sG[(wp * 32 + gid)      * QD + 2 * tg];
    ga0[1] = *(const uint32_t*)&sG[(wp * 32 + gid + 8)  * QD + 2 * tg];
    ga1[0] = *(const uint32_t*)&sG[(wp * 32 + gid + 16) * QD + 2 * tg];
    ga1[1] = *(const uint32_t*)&sG[(wp * 32 + gid + 24) * QD + 2 * tg];

    float o0[8][4], o1[8][4];
#pragma unroll
    for (int n = 0; n < 8; n++)
#pragma unroll
        for (int i = 0; i < 4; i++) { o0[n][i] = 0.f; o1[n][i] = 0.f; }
    float lacc0[4] = {0.f, 0.f, 0.f, 0.f};
    float lacc1[4] = {0.f, 0.f, 0.f, 0.f};

    const int NI = KT / 2;   // 32 iterations per pair
    for (int it = 0; it < NI; it++) {
        int buf = it & 1;
        const uint8_t* hb = &sH[pair][buf][0];

        // Prefetch this pair's next key tile (kt = 2*(it+1)+pair).
        if (it + 1 < NI) {
            long kb = kb0 + (long)(2 * (it + 1) + pair) * BN;
            cp_async16(&sF[pair][buf ^ 1][pt * 8], &g_f[(kb + pt) * QD]);
            long koff = (long)(2 * (it + 1) + pair) * BN;
#pragma unroll
            for (int j = 0; j < 4; j++) {
                int idx = pt + 64 * j;
                int col = idx >> 2, seg = idx & 3;
                cp_async16(&sH[pair][buf ^ 1][col * LDHB + seg * 16],
                           &g_ht[hbase + (long)col * NN + koff + seg * 16]);
            }
            cp_async_commit();
        }

        // F B-fragments (single LDS.32 each).
        uint32_t fb[8];
#pragma unroll
        for (int j = 0; j < 8; j++)
            fb[j] = *(const uint32_t*)&sF[pair][buf][(j * 8 + gid) * QD + 2 * tg];

        // Two 32-key groups per tile.
#pragma unroll
        for (int q = 0; q < 2; q++) {
            // S-MMA + exp + e4m3 pack for slabs kkA=2q, kkB=2q+1, both chunks.
            uint32_t pl[2][2], ph[2][2];   // [slab][chunk]
#pragma unroll
            for (int s = 0; s < 2; s++) {
                int kk = 2 * q + s;
                float s0[4] = {0.f,0.f,0.f,0.f}, s1[4] = {0.f,0.f,0.f,0.f};
                mma_16n8k8(s0, ga0, fb[2 * kk]);
                mma_16n8k8(s1, ga0, fb[2 * kk + 1]);
                pl[s][0] = (uint32_t)pk8(s0[0], s0[1]) | ((uint32_t)pk8(s1[0], s1[1]) << 16);
                ph[s][0] = (uint32_t)pk8(s0[2], s0[3]) | ((uint32_t)pk8(s1[2], s1[3]) << 16);
                float t0[4] = {0.f,0.f,0.f,0.f}, t1[4] = {0.f,0.f,0.f,0.f};
                mma_16n8k8(t0, ga1, fb[2 * kk]);
                mma_16n8k8(t1, ga1, fb[2 * kk + 1]);
                pl[s][1] = (uint32_t)pk8(t0[0], t0[1]) | ((uint32_t)pk8(t1[0], t1[1]) << 16);
                ph[s][1] = (uint32_t)pk8(t0[2], t0[3]) | ((uint32_t)pk8(t1[2], t1[3]) << 16);
            }

            // Assemble k32 e4m3 A-fragments (keys 32q..32q+31) via shfl+prmt.
            uint32_t a0[4], a1[4];
            a0[0] = prmt(__shfl_sync(0xffffffffu, pl[0][0], L0),
                         __shfl_sync(0xffffffffu, pl[0][0], L1), ctl);
            a0[1] = prmt(__shfl_sync(0xffffffffu, ph[0][0], L0),
                         __shfl_sync(0xffffffffu, ph[0][0], L1), ctl);
            a0[2] = prmt(__shfl_sync(0xffffffffu, pl[1][0], L0),
                         __shfl_sync(0xffffffffu, pl[1][0], L1), ctl);
            a0[3] = prmt(__shfl_sync(0xffffffffu, ph[1][0], L0),
                         __shfl_sync(0xffffffffu, ph[1][0], L1), ctl);
            a1[0] = prmt(__shfl_sync(0xffffffffu, pl[0][1], L0),
                         __shfl_sync(0xffffffffu, pl[0][1], L1), ctl);
            a1[1] = prmt(__shfl_sync(0xffffffffu, ph[0][1], L0),
                         __shfl_sync(0xffffffffu, ph[0][1], L1), ctl);
            a1[2] = prmt(__shfl_sync(0xffffffffu, pl[1][1], L0),
                         __shfl_sync(0xffffffffu, pl[1][1], L1), ctl);
            a1[3] = prmt(__shfl_sync(0xffffffffu, ph[1][1], L0),
                         __shfl_sync(0xffffffffu, ph[1][1], L1), ctl);

            // Row-sums of quantized P on the tensor pipe.
            mma_e4m3(lacc0, a0, BONES, BONES);
            mma_e4m3(lacc1, a1, BONES, BONES);

            // PV: B-fragments loaded once, shared by both chunks.
#pragma unroll
            for (int np = 0; np < 8; np++) {
                const uint8_t* colp = hb + (np * 8 + gid) * LDHB + 32 * q + 4 * tg;
                uint32_t b0 = *(const uint32_t*)colp;
                uint32_t b1 = *(const uint32_t*)(colp + 16);
                mma_e4m3(o0[np], a0, b0, b1);
                mma_e4m3(o1[np], a1, b0, b1);
            }
        }

        if (it + 1 < NI) {
            cp_async_wait0();
            asm volatile("bar.sync %0, 64;\n" :: "r"(1 + pair) : "memory");
        }
    }

    // Row-sums live in column 0 of lacc (lanes with tg==0). Broadcast.
    int src = lane & 28;
    float l0 = __shfl_sync(0xffffffffu, lacc0[0], src);
    float l1 = __shfl_sync(0xffffffffu, lacc0[2], src);
    float l2 = __shfl_sync(0xffffffffu, lacc1[0], src);
    float l3 = __shfl_sync(0xffffffffu, lacc1[2], src);

    // Join the two pairs through smem (overlay dead sH buffers).
    __syncthreads();
    float* sO = (float*)&sH[0][0][0];   // 64 x LDO floats (18.4 KB < 20 KB)
    int r0 = wp * 32 + gid;
    if (pair == 1) {
#pragma unroll
        for (int n = 0; n < 8; n++) {
            int col = n * 8 + 2 * tg;
            *(float2*)&sO[(r0)      * LDO + col] = make_float2(o0[n][0], o0[n][1]);
            *(float2*)&sO[(r0 + 8)  * LDO + col] = make_float2(o0[n][2], o0[n][3]);
            *(float2*)&sO[(r0 + 16) * LDO + col] = make_float2(o1[n][0], o1[n][1]);
            *(float2*)&sO[(r0 + 24) * LDO + col] = make_float2(o1[n][2], o1[n][3]);
        }
        if (tg == 0) {
            sL[r0] = l0; sL[r0 + 8] = l1; sL[r0 + 16] = l2; sL[r0 + 24] = l3;
        }
    }
    __syncthreads();
    if (pair == 0) {
        float inv0 = gmm / (l0 + sL[r0]);
        float inv1 = gmm / (l1 + sL[r0 + 8]);
        float inv2 = gmm / (l2 + sL[r0 + 16]);
        float inv3 = gmm / (l3 + sL[r0 + 24]);
        long rg = qbase + r0;
#pragma unroll
        for (int n = 0; n < 8; n++) {
            int col = n * 8 + 2 * tg;
            float2 p0 = *(const float2*)&sO[(r0)      * LDO + col];
            float2 p1 = *(const float2*)&sO[(r0 + 8)  * LDO + col];
            float2 p2 = *(const float2*)&sO[(r0 + 16) * LDO + col];
            float2 p3 = *(const float2*)&sO[(r0 + 24) * LDO + col];
            float2 x0 = *(const float2*)&x[(rg)      * CC + col];
            float2 x1 = *(const float2*)&x[(rg + 8)  * CC + col];
            float2 x2 = *(const float2*)&x[(rg + 16) * CC + col];
            float2 x3 = *(const float2*)&x[(rg + 24) * CC + col];
            float2 v;
            v.x = (o0[n][0] + p0.x) * inv0 + x0.x;
            v.y = (o0[n][1] + p0.y) * inv0 + x0.y;
            *(float2*)&out[(rg)      * CC + col] = v;
            v.x = (o0[n][2] + p1.x) * inv1 + x1.x;
            v.y = (o0[n][3] + p1.y) * inv1 + x1.y;
            *(float2*)&out[(rg + 8)  * CC + col] = v;
            v.x = (o1[n][0] + p2.x) * inv2 + x2.x;
            v.y = (o1[n][1] + p2.y) * inv2 + x2.y;
            *(float2*)&out[(rg + 16) * CC + col] = v;
            v.x = (o1[n][2] + p3.x) * inv3 + x3.x;
            v.y = (o1[n][3] + p3.y) * inv3 + x3.y;
            *(float2*)&out[(rg + 24) * CC + col] = v;
        }
    }
}

// ---------------------------------------------------------------------------

extern "C" void kernel_launch(void* const* d_in, const int* in_sizes, int n_in,
                              void* d_out, int out_size)
{
    const float* x     = (const float*)d_in[0];
    const float* kf    = (const float*)d_in[1];
    const float* kg    = (const float*)d_in[2];
    const float* kh    = (const float*)d_in[3];
    const float* gamma = (const float*)d_in[4];
    float*       out   = (float*)d_out;

    proj_kernel<<<(BB * NN) / 128, 256>>>(x, kf, kg, kh);
    attn_kernel<<<BB * QT, 128>>>(x, gamma, out);
}

// round 11
// speedup vs baseline: 1.2004x; 1.2004x over previous
#include <cuda_runtime.h>
#include <cuda_bf16.h>
#include <stdint.h>

#define BB 8
#define NN 4096
#define CC 64
#define QD 8
#define BM 64          // query rows per block
#define BN 64          // key tile rows
#define QT (NN / BM)
#define KT (NN / BN)
#define LDH 72         // sH leading dim
#define LDO 72         // epilogue O overlay leading dim (floats)
#define LOG2E 1.4426950408889634f

// Static device scratch for projections.
__device__ __nv_bfloat16 g_f[BB * NN * QD];   // 0.5 MB
__device__ __nv_bfloat16 g_g[BB * NN * QD];   // 0.5 MB (pre-scaled by log2e)
__device__ __nv_bfloat16 g_h[BB * NN * CC];   // 4 MB

// ---------------------------------------------------------------------------
// PTX helpers
// ---------------------------------------------------------------------------
__device__ __forceinline__ void mma_16n8k8(float* c, const uint32_t* a, uint32_t b)
{
    asm volatile(
        "mma.sync.aligned.m16n8k8.row.col.f32.bf16.bf16.f32 "
        "{%0,%1,%2,%3}, {%4,%5}, {%6}, {%0,%1,%2,%3};\n"
        : "+f"(c[0]), "+f"(c[1]), "+f"(c[2]), "+f"(c[3])
        : "r"(a[0]), "r"(a[1]), "r"(b));
}

__device__ __forceinline__ void mma_16n8k16(float* c, const uint32_t* a, const uint32_t* b)
{
    asm volatile(
        "mma.sync.aligned.m16n8k16.row.col.f32.bf16.bf16.f32 "
        "{%0,%1,%2,%3}, {%4,%5,%6,%7}, {%8,%9}, {%0,%1,%2,%3};\n"
        : "+f"(c[0]), "+f"(c[1]), "+f"(c[2]), "+f"(c[3])
        : "r"(a[0]), "r"(a[1]), "r"(a[2]), "r"(a[3]), "r"(b[0]), "r"(b[1]));
}

__device__ __forceinline__ void ldsm_x4(uint32_t* r, const void* smem_ptr)
{
    uint32_t addr = (uint32_t)__cvta_generic_to_shared(smem_ptr);
    asm volatile(
        "ldmatrix.sync.aligned.m8n8.x4.shared.b16 {%0,%1,%2,%3}, [%4];\n"
        : "=r"(r[0]), "=r"(r[1]), "=r"(r[2]), "=r"(r[3]) : "r"(addr));
}

__device__ __forceinline__ void ldsm_x4_trans(uint32_t* r, const void* smem_ptr)
{
    uint32_t addr = (uint32_t)__cvta_generic_to_shared(smem_ptr);
    asm volatile(
        "ldmatrix.sync.aligned.m8n8.x4.trans.shared.b16 {%0,%1,%2,%3}, [%4];\n"
        : "=r"(r[0]), "=r"(r[1]), "=r"(r[2]), "=r"(r[3]) : "r"(addr));
}

__device__ __forceinline__ uint32_t pack_bf162(float a, float b)
{
    __nv_bfloat162 t = __floats2bfloat162_rn(a, b);
    return *(uint32_t*)&t;
}

// cvt two fp32 -> bf16x2 (lo, hi), then exp2 both halves in ONE MUFU op.
__device__ __forceinline__ uint32_t ex2_pair(float lo, float hi)
{
    uint32_t t, y;
    asm("cvt.rn.bf16x2.f32 %0, %1, %2;\n" : "=r"(t) : "f"(hi), "f"(lo));
    asm("ex2.approx.ftz.bf16x2 %0, %1;\n" : "=r"(y) : "r"(t));
    return y;
}

// Accumulate both bf16 halves of r into l as exact f32 (bf16 = truncated f32).
__device__ __forceinline__ void acc_bf16x2(float& l, uint32_t r)
{
    l += __uint_as_float(r << 16);
    l += __uint_as_float(r & 0xFFFF0000u);
}

__device__ __forceinline__ void cp_async16(void* smem_dst, const void* gmem_src)
{
    uint32_t d = (uint32_t)__cvta_generic_to_shared(smem_dst);
    asm volatile("cp.async.cg.shared.global [%0], [%1], 16;\n"
                 :: "r"(d), "l"(gmem_src) : "memory");
}
__device__ __forceinline__ void cp_async_commit()
{
    asm volatile("cp.async.commit_group;\n" ::: "memory");
}
__device__ __forceinline__ void cp_async_wait0()
{
    asm volatile("cp.async.wait_group 0;\n" ::: "memory");
}

// ---------------------------------------------------------------------------
// Kernel 1: projections as HMMA GEMM.  [128 rows x 64] @ [64 x 80] per block.
// 256 blocks x 256 threads (8 warps, 16 rows each). Wg pre-scaled by log2e.
// ---------------------------------------------------------------------------
#define LDW 88
#define LDX 72
__global__ __launch_bounds__(256) void proj_kernel(
    const float* __restrict__ x,
    const float* __restrict__ kf,
    const float* __restrict__ kg,
    const float* __restrict__ kh)
{
    __shared__ __nv_bfloat16 sW[64 * LDW];    // row c: d 0-7 f, 8-15 g(scaled), 16-79 h
    __shared__ __nv_bfloat16 sX[128 * LDX];

    int tid  = threadIdx.x;
    int lane = tid & 31;
    int w    = tid >> 5;
    int gid  = lane >> 2;
    int tg   = lane & 3;

    for (int idx = tid; idx < 64 * 80; idx += 256) {
        int c = idx / 80, d = idx % 80;
        float v;
        if (d < 8)       v = kf[c * 8 + d];
        else if (d < 16) v = kg[c * 8 + (d - 8)] * LOG2E;
        else             v = kh[c * 64 + (d - 16)];
        sW[c * LDW + d] = __float2bfloat16(v);
    }
    long base = (long)blockIdx.x * 128;
    const float4* xg = (const float4*)(x + base * 64);
    for (int i = tid; i < 2048; i += 256) {
        int r = i >> 4, c4 = (i & 15) * 4;
        float4 v = xg[i];
        __nv_bfloat162* dst = (__nv_bfloat162*)&sX[r * LDX + c4];
        dst[0] = __floats2bfloat162_rn(v.x, v.y);
        dst[1] = __floats2bfloat162_rn(v.z, v.w);
    }
    __syncthreads();

    float c[10][4];
#pragma unroll
    for (int n = 0; n < 10; n++)
#pragma unroll
        for (int i = 0; i < 4; i++) c[n][i] = 0.f;

#pragma unroll
    for (int kk = 0; kk < 4; kk++) {
        uint32_t a[4];
        ldsm_x4(a, &sX[(w * 16 + (lane & 15)) * LDX + kk * 16 + (lane >> 4) * 8]);
#pragma unroll
        for (int np = 0; np < 5; np++) {
            uint32_t bfr[4];
            ldsm_x4_trans(bfr,
                &sW[(kk * 16 + (lane & 15)) * LDW + np * 16 + (lane >> 4) * 8]);
            mma_16n8k16(c[2 * np],     a, &bfr[0]);
            mma_16n8k16(c[2 * np + 1], a, &bfr[2]);
        }
    }

    // Fragment-direct scattered stores: d = 16*np + 8*h + 2*tg (static routing).
    long r0 = base + w * 16 + gid;
    long r1 = r0 + 8;
#pragma unroll
    for (int np = 0; np < 5; np++) {
#pragma unroll
        for (int h = 0; h < 2; h++) {
            int dbase = 16 * np + 8 * h;
            uint32_t u0 = pack_bf162(c[2 * np + h][0], c[2 * np + h][1]);
            uint32_t u1 = pack_bf162(c[2 * np + h][2], c[2 * np + h][3]);
            if (dbase == 0) {
                *(uint32_t*)&g_f[r0 * QD + 2 * tg] = u0;
                *(uint32_t*)&g_f[r1 * QD + 2 * tg] = u1;
            } else if (dbase == 8) {
                *(uint32_t*)&g_g[r0 * QD + 2 * tg] = u0;
                *(uint32_t*)&g_g[r1 * QD + 2 * tg] = u1;
            } else {
                int d = dbase - 16 + 2 * tg;
                *(uint32_t*)&g_h[r0 * CC + d] = u0;
                *(uint32_t*)&g_h[r1 * CC + d] = u1;
            }
        }
    }
}

// ---------------------------------------------------------------------------
// Kernel 2: flash attention. 128 threads = 2 key-parity pairs (2 warps each).
// Pair p (warps 2p, 2p+1) handles key tiles kt = p, p+2, ...; warp-in-pair wp
// covers rows [wp*32, wp*32+32) as two m16 chunks sharing every H B-fragment.
// exp via bf16x2 ex2 (2 exps/MUFU op); row-sums on the FMA/ALU pipes by
// unpacking the packed-P registers (bf16 = f32 high bits) — exact same values
// the PV MMA consumes, and 8 fewer tensor ops per iteration.
// ---------------------------------------------------------------------------
__global__ __launch_bounds__(128) void attn_kernel(
    const float* __restrict__ x,
    const float* __restrict__ gamma_p,
    float* __restrict__ out)
{
    __shared__ __nv_bfloat16 sG[BM * QD];             // 1 KB
    __shared__ __nv_bfloat16 sF[2][2][BN * QD];       // 4 KB   [pair][buf]
    __shared__ __nv_bfloat16 sH[2][2][BN * LDH];      // 36 KB  [pair][buf]
    __shared__ float         sL[BM];

    int tid  = threadIdx.x;
    int lane = tid & 31;
    int w    = tid >> 5;          // 0..3
    int pair = w >> 1;            // key-tile parity this warp handles
    int wp   = w & 1;             // warp-in-pair: row half
    int pt   = tid & 63;          // pair-local thread id
    int gid  = lane >> 2;
    int tg   = lane & 3;
    int b    = blockIdx.x / QT;
    int qt   = blockIdx.x % QT;
    long qbase = (long)b * NN + (long)qt * BM;
    long kb0   = (long)b * NN;

    float gmm = gamma_p[0];

    // Prologue: G tile + each pair's first key tile (kt = pair).
    if (tid < 64) cp_async16(&sG[tid * 8], &g_g[(qbase + tid) * QD]);
    {
        long kb = kb0 + (long)pair * BN;
        cp_async16(&sF[pair][0][pt * 8], &g_f[(kb + pt) * QD]);
#pragma unroll
        for (int i = 0; i < 8; i++) {
            int idx = pt + 64 * i;
            cp_async16(&sH[pair][0][(idx >> 3) * LDH + (idx & 7) * 8],
                       &g_h[kb * CC + idx * 8]);
        }
    }
    cp_async_commit();
    cp_async_wait0();
    __syncthreads();

    // G A-fragments for rows wp*32 + {gid, gid+8, gid+16, gid+24}.
    uint32_t ga0[2], ga1[2];
    ga0[0] = *(const uint32_t*)&sG[(wp * 32 + gid)      * QD + 2 * tg];
    ga0[1] = *(const uint32_t*)&sG[(wp * 32 + gid + 8)  * QD + 2 * tg];
    ga1[0] = *(const uint32_t*)&sG[(wp * 32 + gid + 16) * QD + 2 * tg];
    ga1[1] = *(const uint32_t*)&sG[(wp * 32 + gid + 24) * QD + 2 * tg];

    float o0[8][4], o1[8][4];
#pragma unroll
    for (int n = 0; n < 8; n++)
#pragma unroll
        for (int i = 0; i < 4; i++) { o0[n][i] = 0.f; o1[n][i] = 0.f; }
    float l0 = 0.f, l1 = 0.f, l2 = 0.f, l3 = 0.f;

    const int NI = KT / 2;   // 32 iterations per pair
    for (int i = 0; i < NI; i++) {
        int buf = i & 1;
        const __nv_bfloat16* hb = &sH[pair][buf][0];

        // Prefetch this pair's next key tile (kt = 2*(i+1)+pair).
        if (i + 1 < NI) {
            long kb = kb0 + (long)(2 * (i + 1) + pair) * BN;
            cp_async16(&sF[pair][buf ^ 1][pt * 8], &g_f[(kb + pt) * QD]);
#pragma unroll
            for (int j = 0; j < 8; j++) {
                int idx = pt + 64 * j;
                cp_async16(&sH[pair][buf ^ 1][(idx >> 3) * LDH + (idx & 7) * 8],
                           &g_h[kb * CC + idx * 8]);
            }
            cp_async_commit();
        }

        // F B-fragments (single LDS.32 each).
        uint32_t fb[8];
#pragma unroll
        for (int j = 0; j < 8; j++)
            fb[j] = *(const uint32_t*)&sF[pair][buf][(j * 8 + gid) * QD + 2 * tg];

        // Per 16-key slab: S-MMA -> bf16x2 exp -> rowsum (FMA pipe) + PV-MMA.
#pragma unroll
        for (int kk = 0; kk < 4; kk++) {
            float s00[4] = {0.f,0.f,0.f,0.f}, s01[4] = {0.f,0.f,0.f,0.f};
            float s10[4] = {0.f,0.f,0.f,0.f}, s11[4] = {0.f,0.f,0.f,0.f};
            mma_16n8k8(s00, ga0, fb[2 * kk]);
            mma_16n8k8(s01, ga0, fb[2 * kk + 1]);
            mma_16n8k8(s10, ga1, fb[2 * kk]);
            mma_16n8k8(s11, ga1, fb[2 * kk + 1]);

            uint32_t a0[4], a1[4];
            a0[0] = ex2_pair(s00[0], s00[1]);
            a0[1] = ex2_pair(s00[2], s00[3]);
            a0[2] = ex2_pair(s01[0], s01[1]);
            a0[3] = ex2_pair(s01[2], s01[3]);
            a1[0] = ex2_pair(s10[0], s10[1]);
            a1[1] = ex2_pair(s10[2], s10[3]);
            a1[2] = ex2_pair(s11[0], s11[1]);
            a1[3] = ex2_pair(s11[2], s11[3]);

            // Row-sums of the exact rounded-P values on the FMA/ALU pipes.
            acc_bf16x2(l0, a0[0]); acc_bf16x2(l0, a0[2]);   // rows wp*32+gid
            acc_bf16x2(l1, a0[1]); acc_bf16x2(l1, a0[3]);   // rows wp*32+gid+8
            acc_bf16x2(l2, a1[0]); acc_bf16x2(l2, a1[2]);   // rows wp*32+gid+16
            acc_bf16x2(l3, a1[1]); acc_bf16x2(l3, a1[3]);   // rows wp*32+gid+24

#pragma unroll
            for (int np = 0; np < 4; np++) {
                uint32_t bfr[4];
                ldsm_x4_trans(bfr,
                    &hb[(kk * 16 + (lane & 15)) * LDH + np * 16 + (lane >> 4) * 8]);
                mma_16n8k16(o0[2 * np],     a0, &bfr[0]);
                mma_16n8k16(o0[2 * np + 1], a0, &bfr[2]);
                mma_16n8k16(o1[2 * np],     a1, &bfr[0]);
                mma_16n8k16(o1[2 * np + 1], a1, &bfr[2]);
            }
        }

        if (i + 1 < NI) {
            cp_async_wait0();
            asm volatile("bar.sync %0, 64;\n" :: "r"(1 + pair) : "memory");
        }
    }

    // Reduce row-sums across the 4 lanes of each row group.
    l0 += __shfl_xor_sync(0xffffffffu, l0, 1); l0 += __shfl_xor_sync(0xffffffffu, l0, 2);
    l1 += __shfl_xor_sync(0xffffffffu, l1, 1); l1 += __shfl_xor_sync(0xffffffffu, l1, 2);
    l2 += __shfl_xor_sync(0xffffffffu, l2, 1); l2 += __shfl_xor_sync(0xffffffffu, l2, 2);
    l3 += __shfl_xor_sync(0xffffffffu, l3, 1); l3 += __shfl_xor_sync(0xffffffffu, l3, 2);

    // Join the two pairs: pair 1 parks partial O + l in smem (overlaying the
    // dead sH buffers), pair 0 combines and writes out.
    __syncthreads();
    float* sO = (float*)&sH[0][0][0];   // 64 x LDO floats (< 36 KB)
    int r0 = wp * 32 + gid;
    if (pair == 1) {
#pragma unroll
        for (int n = 0; n < 8; n++) {
            int col = n * 8 + 2 * tg;
            *(float2*)&sO[(r0)      * LDO + col] = make_float2(o0[n][0], o0[n][1]);
            *(float2*)&sO[(r0 + 8)  * LDO + col] = make_float2(o0[n][2], o0[n][3]);
            *(float2*)&sO[(r0 + 16) * LDO + col] = make_float2(o1[n][0], o1[n][1]);
            *(float2*)&sO[(r0 + 24) * LDO + col] = make_float2(o1[n][2], o1[n][3]);
        }
        if (tg == 0) {
            sL[r0] = l0; sL[r0 + 8] = l1; sL[r0 + 16] = l2; sL[r0 + 24] = l3;
        }
    }
    __syncthreads();
    if (pair == 0) {
        float inv0 = gmm / (l0 + sL[r0]);
        float inv1 = gmm / (l1 + sL[r0 + 8]);
        float inv2 = gmm / (l2 + sL[r0 + 16]);
        float inv3 = gmm / (l3 + sL[r0 + 24]);
        long rg = qbase + r0;
#pragma unroll
        for (int n = 0; n < 8; n++) {
            int col = n * 8 + 2 * tg;
            float2 p0 = *(const float2*)&sO[(r0)      * LDO + col];
            float2 p1 = *(const float2*)&sO[(r0 + 8)  * LDO + col];
            float2 p2 = *(const float2*)&sO[(r0 + 16) * LDO + col];
            float2 p3 = *(const float2*)&sO[(r0 + 24) * LDO + col];
            float2 x0 = *(const float2*)&x[(rg)      * CC + col];
            float2 x1 = *(const float2*)&x[(rg + 8)  * CC + col];
            float2 x2 = *(const float2*)&x[(rg + 16) * CC + col];
            float2 x3 = *(const float2*)&x[(rg + 24) * CC + col];
            float2 v;
            v.x = (o0[n][0] + p0.x) * inv0 + x0.x;
            v.y = (o0[n][1] + p0.y) * inv0 + x0.y;
            *(float2*)&out[(rg)      * CC + col] = v;
            v.x = (o0[n][2] + p1.x) * inv1 + x1.x;
            v.y = (o0[n][3] + p1.y) * inv1 + x1.y;
            *(float2*)&out[(rg + 8)  * CC + col] = v;
            v.x = (o1[n][0] + p2.x) * inv2 + x2.x;
            v.y = (o1[n][1] + p2.y) * inv2 + x2.y;
            *(float2*)&out[(rg + 16) * CC + col] = v;
            v.x = (o1[n][2] + p3.x) * inv3 + x3.x;
            v.y = (o1[n][3] + p3.y) * inv3 + x3.y;
            *(float2*)&out[(rg + 24) * CC + col] = v;
        }
    }
}

// ---------------------------------------------------------------------------

extern "C" void kernel_launch(void* const* d_in, const int* in_sizes, int n_in,
                              void* d_out, int out_size)
{
    const float* x     = (const float*)d_in[0];
    const float* kf    = (const float*)d_in[1];
    const float* kg    = (const float*)d_in[2];
    const float* kh    = (const float*)d_in[3];
    const float* gamma = (const float*)d_in[4];
    float*       out   = (float*)d_out;

    proj_kernel<<<(BB * NN) / 128, 256>>>(x, kf, kg, kh);
    attn_kernel<<<BB * QT, 128>>>(x, gamma, out);
}

// round 12
// speedup vs baseline: 1.3536x; 1.1276x over previous
#include <cuda_runtime.h>
#include <cuda_bf16.h>
#include <stdint.h>

#define BB 8
#define NN 4096
#define CC 64
#define QD 8
#define BM 64          // query rows per block
#define BN 64          // key tile rows
#define QT (NN / BM)
#define KT (NN / BN)
#define LDH 72         // sH leading dim
#define LDO 72         // epilogue O overlay leading dim (floats)
#define LOG2E 1.4426950408889634f

// Static device scratch for projections.
__device__ __nv_bfloat16 g_f[BB * NN * QD];   // 0.5 MB
__device__ __nv_bfloat16 g_g[BB * NN * QD];   // 0.5 MB (pre-scaled by log2e)
__device__ __nv_bfloat16 g_h[BB * NN * CC];   // 4 MB

// ---------------------------------------------------------------------------
// PTX helpers
// ---------------------------------------------------------------------------
__device__ __forceinline__ void mma_16n8k8(float* c, const uint32_t* a, uint32_t b)
{
    asm volatile(
        "mma.sync.aligned.m16n8k8.row.col.f32.bf16.bf16.f32 "
        "{%0,%1,%2,%3}, {%4,%5}, {%6}, {%0,%1,%2,%3};\n"
        : "+f"(c[0]), "+f"(c[1]), "+f"(c[2]), "+f"(c[3])
        : "r"(a[0]), "r"(a[1]), "r"(b));
}

__device__ __forceinline__ void mma_16n8k16(float* c, const uint32_t* a, const uint32_t* b)
{
    asm volatile(
        "mma.sync.aligned.m16n8k16.row.col.f32.bf16.bf16.f32 "
        "{%0,%1,%2,%3}, {%4,%5,%6,%7}, {%8,%9}, {%0,%1,%2,%3};\n"
        : "+f"(c[0]), "+f"(c[1]), "+f"(c[2]), "+f"(c[3])
        : "r"(a[0]), "r"(a[1]), "r"(a[2]), "r"(a[3]), "r"(b[0]), "r"(b[1]));
}

__device__ __forceinline__ void ldsm_x4(uint32_t* r, const void* smem_ptr)
{
    uint32_t addr = (uint32_t)__cvta_generic_to_shared(smem_ptr);
    asm volatile(
        "ldmatrix.sync.aligned.m8n8.x4.shared.b16 {%0,%1,%2,%3}, [%4];\n"
        : "=r"(r[0]), "=r"(r[1]), "=r"(r[2]), "=r"(r[3]) : "r"(addr));
}

__device__ __forceinline__ void ldsm_x4_trans(uint32_t* r, const void* smem_ptr)
{
    uint32_t addr = (uint32_t)__cvta_generic_to_shared(smem_ptr);
    asm volatile(
        "ldmatrix.sync.aligned.m8n8.x4.trans.shared.b16 {%0,%1,%2,%3}, [%4];\n"
        : "=r"(r[0]), "=r"(r[1]), "=r"(r[2]), "=r"(r[3]) : "r"(addr));
}

__device__ __forceinline__ uint32_t pack_bf162(float a, float b)
{
    __nv_bfloat162 t = __floats2bfloat162_rn(a, b);
    return *(uint32_t*)&t;
}

// cvt two fp32 -> bf16x2 (lo, hi), then exp2 both halves in ONE MUFU op.
__device__ __forceinline__ uint32_t ex2_pair(float lo, float hi)
{
    uint32_t t, y;
    asm("cvt.rn.bf16x2.f32 %0, %1, %2;\n" : "=r"(t) : "f"(hi), "f"(lo));
    asm("ex2.approx.ftz.bf16x2 %0, %1;\n" : "=r"(y) : "r"(t));
    return y;
}

__device__ __forceinline__ void cp_async16(void* smem_dst, const void* gmem_src)
{
    uint32_t d = (uint32_t)__cvta_generic_to_shared(smem_dst);
    asm volatile("cp.async.cg.shared.global [%0], [%1], 16;\n"
                 :: "r"(d), "l"(gmem_src) : "memory");
}
__device__ __forceinline__ void cp_async_commit()
{
    asm volatile("cp.async.commit_group;\n" ::: "memory");
}
__device__ __forceinline__ void cp_async_wait0()
{
    asm volatile("cp.async.wait_group 0;\n" ::: "memory");
}

// ---------------------------------------------------------------------------
// Kernel 1: projections as HMMA GEMM.  [64 rows x 64] @ [64 x 80] per block.
// 512 blocks x 128 threads (4 warps, 16 rows each) — finer grid granularity
// than the 256x256 variant (less ragged final wave), float4-vectorized
// weight staging. Wg pre-scaled by log2e.
// ---------------------------------------------------------------------------
#define LDW 88
#define LDX 72
__global__ __launch_bounds__(128) void proj_kernel(
    const float* __restrict__ x,
    const float* __restrict__ kf,
    const float* __restrict__ kg,
    const float* __restrict__ kh)
{
    __shared__ __nv_bfloat16 sW[64 * LDW];    // row c: d 0-7 f, 8-15 g(scaled), 16-79 h
    __shared__ __nv_bfloat16 sX[64 * LDX];

    int tid  = threadIdx.x;
    int lane = tid & 31;
    int w    = tid >> 5;
    int gid  = lane >> 2;
    int tg   = lane & 3;

    // Vectorized weight staging: flat float4 index over [kf | kg | kh].
    // kf: 512 f32 (128 f4), kg: 512 (128 f4), kh: 4096 (1024 f4).
    for (int i = tid; i < 1280; i += 128) {
        float4 v;
        int c, d;
        float sc = 1.f;
        if (i < 128) {
            v = ((const float4*)kf)[i];
            int e = i * 4;  c = e >> 3;  d = e & 7;
        } else if (i < 256) {
            v = ((const float4*)kg)[i - 128];
            int e = (i - 128) * 4;  c = e >> 3;  d = (e & 7) + 8;
            sc = LOG2E;
        } else {
            v = ((const float4*)kh)[i - 256];
            int e = (i - 256) * 4;  c = e >> 6;  d = (e & 63) + 16;
        }
        __nv_bfloat16* dst = &sW[c * LDW + d];
        dst[0] = __float2bfloat16(v.x * sc);
        dst[1] = __float2bfloat16(v.y * sc);
        dst[2] = __float2bfloat16(v.z * sc);
        dst[3] = __float2bfloat16(v.w * sc);
    }
    long base = (long)blockIdx.x * 64;
    const float4* xg = (const float4*)(x + base * 64);
    for (int i = tid; i < 1024; i += 128) {
        int r = i >> 4, c4 = (i & 15) * 4;
        float4 v = xg[i];
        __nv_bfloat162* dst = (__nv_bfloat162*)&sX[r * LDX + c4];
        dst[0] = __floats2bfloat162_rn(v.x, v.y);
        dst[1] = __floats2bfloat162_rn(v.z, v.w);
    }
    __syncthreads();

    float c[10][4];
#pragma unroll
    for (int n = 0; n < 10; n++)
#pragma unroll
        for (int i = 0; i < 4; i++) c[n][i] = 0.f;

#pragma unroll
    for (int kk = 0; kk < 4; kk++) {
        uint32_t a[4];
        ldsm_x4(a, &sX[(w * 16 + (lane & 15)) * LDX + kk * 16 + (lane >> 4) * 8]);
#pragma unroll
        for (int np = 0; np < 5; np++) {
            uint32_t bfr[4];
            ldsm_x4_trans(bfr,
                &sW[(kk * 16 + (lane & 15)) * LDW + np * 16 + (lane >> 4) * 8]);
            mma_16n8k16(c[2 * np],     a, &bfr[0]);
            mma_16n8k16(c[2 * np + 1], a, &bfr[2]);
        }
    }

    // Fragment-direct scattered stores: d = 16*np + 8*h + 2*tg (static routing).
    long r0 = base + w * 16 + gid;
    long r1 = r0 + 8;
#pragma unroll
    for (int np = 0; np < 5; np++) {
#pragma unroll
        for (int h = 0; h < 2; h++) {
            int dbase = 16 * np + 8 * h;
            uint32_t u0 = pack_bf162(c[2 * np + h][0], c[2 * np + h][1]);
            uint32_t u1 = pack_bf162(c[2 * np + h][2], c[2 * np + h][3]);
            if (dbase == 0) {
                *(uint32_t*)&g_f[r0 * QD + 2 * tg] = u0;
                *(uint32_t*)&g_f[r1 * QD + 2 * tg] = u1;
            } else if (dbase == 8) {
                *(uint32_t*)&g_g[r0 * QD + 2 * tg] = u0;
                *(uint32_t*)&g_g[r1 * QD + 2 * tg] = u1;
            } else {
                int d = dbase - 16 + 2 * tg;
                *(uint32_t*)&g_h[r0 * CC + d] = u0;
                *(uint32_t*)&g_h[r1 * CC + d] = u1;
            }
        }
    }
}

// ---------------------------------------------------------------------------
// Kernel 2: flash attention (R5 structure — measured best). 128 threads =
// 2 key-parity pairs (2 warps each). Pair p handles key tiles kt = p, p+2,
// ...; warp-in-pair wp covers rows [wp*32, wp*32+32) as two m16 chunks
// sharing every H B-fragment. Row-sums on the tensor pipe via ones-column;
// exp via bf16x2 ex2 (2 exps per MUFU op). Pairs joined through smem.
// ---------------------------------------------------------------------------
__global__ __launch_bounds__(128) void attn_kernel(
    const float* __restrict__ x,
    const float* __restrict__ gamma_p,
    float* __restrict__ out)
{
    __shared__ __nv_bfloat16 sG[BM * QD];             // 1 KB
    __shared__ __nv_bfloat16 sF[2][2][BN * QD];       // 4 KB   [pair][buf]
    __shared__ __nv_bfloat16 sH[2][2][BN * LDH];      // 36 KB  [pair][buf]
    __shared__ float         sL[BM];

    int tid  = threadIdx.x;
    int lane = tid & 31;
    int w    = tid >> 5;          // 0..3
    int pair = w >> 1;            // key-tile parity this warp handles
    int wp   = w & 1;             // warp-in-pair: row half
    int pt   = tid & 63;          // pair-local thread id
    int gid  = lane >> 2;
    int tg   = lane & 3;
    int b    = blockIdx.x / QT;
    int qt   = blockIdx.x % QT;
    long qbase = (long)b * NN + (long)qt * BM;
    long kb0   = (long)b * NN;

    float gmm = gamma_p[0];

    // Ones B-fragment for rowsum MMA: column n=0 of B[k,n] = 1.0 (bf16).
    uint32_t one2 = (lane < 4) ? 0x3F803F80u : 0u;
    uint32_t bones[2] = { one2, one2 };

    // Prologue: G tile + each pair's first key tile (kt = pair).
    if (tid < 64) cp_async16(&sG[tid * 8], &g_g[(qbase + tid) * QD]);
    {
        long kb = kb0 + (long)pair * BN;
        cp_async16(&sF[pair][0][pt * 8], &g_f[(kb + pt) * QD]);
#pragma unroll
        for (int i = 0; i < 8; i++) {
            int idx = pt + 64 * i;
            cp_async16(&sH[pair][0][(idx >> 3) * LDH + (idx & 7) * 8],
                       &g_h[kb * CC + idx * 8]);
        }
    }
    cp_async_commit();
    cp_async_wait0();
    __syncthreads();

    // G A-fragments for rows wp*32 + {gid, gid+8, gid+16, gid+24}.
    uint32_t ga0[2], ga1[2];
    ga0[0] = *(const uint32_t*)&sG[(wp * 32 + gid)      * QD + 2 * tg];
    ga0[1] = *(const uint32_t*)&sG[(wp * 32 + gid + 8)  * QD + 2 * tg];
    ga1[0] = *(const uint32_t*)&sG[(wp * 32 + gid + 16) * QD + 2 * tg];
    ga1[1] = *(const uint32_t*)&sG[(wp * 32 + gid + 24) * QD + 2 * tg];

    float o0[8][4], o1[8][4];
#pragma unroll
    for (int n = 0; n < 8; n++)
#pragma unroll
        for (int i = 0; i < 4; i++) { o0[n][i] = 0.f; o1[n][i] = 0.f; }
    float lacc0[4] = {0.f, 0.f, 0.f, 0.f};
    float lacc1[4] = {0.f, 0.f, 0.f, 0.f};

    const int NI = KT / 2;   // 32 iterations per pair
    for (int i = 0; i < NI; i++) {
        int buf = i & 1;
        const __nv_bfloat16* hb = &sH[pair][buf][0];

        // Prefetch this pair's next key tile (kt = 2*(i+1)+pair).
        if (i + 1 < NI) {
            long kb = kb0 + (long)(2 * (i + 1) + pair) * BN;
            cp_async16(&sF[pair][buf ^ 1][pt * 8], &g_f[(kb + pt) * QD]);
#pragma unroll
            for (int j = 0; j < 8; j++) {
                int idx = pt + 64 * j;
                cp_async16(&sH[pair][buf ^ 1][(idx >> 3) * LDH + (idx & 7) * 8],
                           &g_h[kb * CC + idx * 8]);
            }
            cp_async_commit();
        }

        // F B-fragments (single LDS.32 each).
        uint32_t fb[8];
#pragma unroll
        for (int j = 0; j < 8; j++)
            fb[j] = *(const uint32_t*)&sF[pair][buf][(j * 8 + gid) * QD + 2 * tg];

        // Per 16-key slab: S-MMA -> bf16x2 exp -> rowsum-MMA + PV-MMA.
#pragma unroll
        for (int kk = 0; kk < 4; kk++) {
            float s00[4] = {0.f,0.f,0.f,0.f}, s01[4] = {0.f,0.f,0.f,0.f};
            float s10[4] = {0.f,0.f,0.f,0.f}, s11[4] = {0.f,0.f,0.f,0.f};
            mma_16n8k8(s00, ga0, fb[2 * kk]);
            mma_16n8k8(s01, ga0, fb[2 * kk + 1]);
            mma_16n8k8(s10, ga1, fb[2 * kk]);
            mma_16n8k8(s11, ga1, fb[2 * kk + 1]);

            uint32_t a0[4], a1[4];
            a0[0] = ex2_pair(s00[0], s00[1]);
            a0[1] = ex2_pair(s00[2], s00[3]);
            a0[2] = ex2_pair(s01[0], s01[1]);
            a0[3] = ex2_pair(s01[2], s01[3]);
            a1[0] = ex2_pair(s10[0], s10[1]);
            a1[1] = ex2_pair(s10[2], s10[3]);
            a1[2] = ex2_pair(s11[0], s11[1]);
            a1[3] = ex2_pair(s11[2], s11[3]);

            // Row-sums on the tensor pipe (exact sum of the rounded P).
            mma_16n8k16(lacc0, a0, bones);
            mma_16n8k16(lacc1, a1, bones);

#pragma unroll
            for (int np = 0; np < 4; np++) {
                uint32_t bfr[4];
                ldsm_x4_trans(bfr,
                    &hb[(kk * 16 + (lane & 15)) * LDH + np * 16 + (lane >> 4) * 8]);
                mma_16n8k16(o0[2 * np],     a0, &bfr[0]);
                mma_16n8k16(o0[2 * np + 1], a0, &bfr[2]);
                mma_16n8k16(o1[2 * np],     a1, &bfr[0]);
                mma_16n8k16(o1[2 * np + 1], a1, &bfr[2]);
            }
        }

        if (i + 1 < NI) {
            cp_async_wait0();
            asm volatile("bar.sync %0, 64;\n" :: "r"(1 + pair) : "memory");
        }
    }

    // Row-sums live in column 0 of lacc (lanes with tg==0). Broadcast to the
    // 4 lanes of each row group.
    int src = lane & 28;
    float l0 = __shfl_sync(0xffffffffu, lacc0[0], src);
    float l1 = __shfl_sync(0xffffffffu, lacc0[2], src);
    float l2 = __shfl_sync(0xffffffffu, lacc1[0], src);
    float l3 = __shfl_sync(0xffffffffu, lacc1[2], src);

    // Join the two pairs: pair 1 parks partial O + l in smem (overlaying the
    // dead sH buffers), pair 0 combines and writes out.
    __syncthreads();
    float* sO = (float*)&sH[0][0][0];   // 64 x LDO floats (< 36 KB)
    int r0 = wp * 32 + gid;
    if (pair == 1) {
#pragma unroll
        for (int n = 0; n < 8; n++) {
            int col = n * 8 + 2 * tg;
            *(float2*)&sO[(r0)      * LDO + col] = make_float2(o0[n][0], o0[n][1]);
            *(float2*)&sO[(r0 + 8)  * LDO + col] = make_float2(o0[n][2], o0[n][3]);
            *(float2*)&sO[(r0 + 16) * LDO + col] = make_float2(o1[n][0], o1[n][1]);
            *(float2*)&sO[(r0 + 24) * LDO + col] = make_float2(o1[n][2], o1[n][3]);
        }
        if (tg == 0) {
            sL[r0] = l0; sL[r0 + 8] = l1; sL[r0 + 16] = l2; sL[r0 + 24] = l3;
        }
    }
    __syncthreads();
    if (pair == 0) {
        float inv0 = gmm / (l0 + sL[r0]);
        float inv1 = gmm / (l1 + sL[r0 + 8]);
        float inv2 = gmm / (l2 + sL[r0 + 16]);
        float inv3 = gmm / (l3 + sL[r0 + 24]);
        long rg = qbase + r0;
#pragma unroll
        for (int n = 0; n < 8; n++) {
            int col = n * 8 + 2 * tg;
            float2 p0 = *(const float2*)&sO[(r0)      * LDO + col];
            float2 p1 = *(const float2*)&sO[(r0 + 8)  * LDO + col];
            float2 p2 = *(const float2*)&sO[(r0 + 16) * LDO + col];
            float2 p3 = *(const float2*)&sO[(r0 + 24) * LDO + col];
            float2 x0 = *(const float2*)&x[(rg)      * CC + col];
            float2 x1 = *(const float2*)&x[(rg + 8)  * CC + col];
            float2 x2 = *(const float2*)&x[(rg + 16) * CC + col];
            float2 x3 = *(const float2*)&x[(rg + 24) * CC + col];
            float2 v;
            v.x = (o0[n][0] + p0.x) * inv0 + x0.x;
            v.y = (o0[n][1] + p0.y) * inv0 + x0.y;
            *(float2*)&out[(rg)      * CC + col] = v;
            v.x = (o0[n][2] + p1.x) * inv1 + x1.x;
            v.y = (o0[n][3] + p1.y) * inv1 + x1.y;
            *(float2*)&out[(rg + 8)  * CC + col] = v;
            v.x = (o1[n][0] + p2.x) * inv2 + x2.x;
            v.y = (o1[n][1] + p2.y) * inv2 + x2.y;
            *(float2*)&out[(rg + 16) * CC + col] = v;
            v.x = (o1[n][2] + p3.x) * inv3 + x3.x;
            v.y = (o1[n][3] + p3.y) * inv3 + x3.y;
            *(float2*)&out[(rg + 24) * CC + col] = v;
        }
    }
}

// ---------------------------------------------------------------------------

extern "C" void kernel_launch(void* const* d_in, const int* in_sizes, int n_in,
                              void* d_out, int out_size)
{
    const float* x     = (const float*)d_in[0];
    const float* kf    = (const float*)d_in[1];
    const float* kg    = (const float*)d_in[2];
    const float* kh    = (const float*)d_in[3];
    const float* gamma = (const float*)d_in[4];
    float*       out   = (float*)d_out;

    proj_kernel<<<(BB * NN) / 64, 128>>>(x, kf, kg, kh);
    attn_kernel<<<BB * QT, 128>>>(x, gamma, out);
}

// round 14
// speedup vs baseline: 1.3920x; 1.0284x over previous
#include <cuda_runtime.h>
#include <cuda_bf16.h>
#include <stdint.h>

#define BB 8
#define NN 4096
#define CC 64
#define QD 8
#define BM 64          // query rows per block
#define BN 64          // key tile rows
#define QT (NN / BM)
#define KT (NN / BN)
#define LDH 72         // sH leading dim
#define LDO 72         // epilogue O overlay leading dim (floats)
#define LOG2E 1.4426950408889634f

// Static device scratch for projections.
__device__ __nv_bfloat16 g_f[BB * NN * QD];   // 0.5 MB
__device__ __nv_bfloat16 g_g[BB * NN * QD];   // 0.5 MB (pre-scaled by log2e)
__device__ __nv_bfloat16 g_h[BB * NN * CC];   // 4 MB

// ---------------------------------------------------------------------------
// PTX helpers
// ---------------------------------------------------------------------------
__device__ __forceinline__ void mma_16n8k8(float* c, const uint32_t* a, uint32_t b)
{
    asm volatile(
        "mma.sync.aligned.m16n8k8.row.col.f32.bf16.bf16.f32 "
        "{%0,%1,%2,%3}, {%4,%5}, {%6}, {%0,%1,%2,%3};\n"
        : "+f"(c[0]), "+f"(c[1]), "+f"(c[2]), "+f"(c[3])
        : "r"(a[0]), "r"(a[1]), "r"(b));
}

__device__ __forceinline__ void mma_16n8k16(float* c, const uint32_t* a, const uint32_t* b)
{
    asm volatile(
        "mma.sync.aligned.m16n8k16.row.col.f32.bf16.bf16.f32 "
        "{%0,%1,%2,%3}, {%4,%5,%6,%7}, {%8,%9}, {%0,%1,%2,%3};\n"
        : "+f"(c[0]), "+f"(c[1]), "+f"(c[2]), "+f"(c[3])
        : "r"(a[0]), "r"(a[1]), "r"(a[2]), "r"(a[3]), "r"(b[0]), "r"(b[1]));
}

__device__ __forceinline__ void ldsm_x4(uint32_t* r, const void* smem_ptr)
{
    uint32_t addr = (uint32_t)__cvta_generic_to_shared(smem_ptr);
    asm volatile(
        "ldmatrix.sync.aligned.m8n8.x4.shared.b16 {%0,%1,%2,%3}, [%4];\n"
        : "=r"(r[0]), "=r"(r[1]), "=r"(r[2]), "=r"(r[3]) : "r"(addr));
}

__device__ __forceinline__ void ldsm_x4_trans(uint32_t* r, const void* smem_ptr)
{
    uint32_t addr = (uint32_t)__cvta_generic_to_shared(smem_ptr);
    asm volatile(
        "ldmatrix.sync.aligned.m8n8.x4.trans.shared.b16 {%0,%1,%2,%3}, [%4];\n"
        : "=r"(r[0]), "=r"(r[1]), "=r"(r[2]), "=r"(r[3]) : "r"(addr));
}

__device__ __forceinline__ uint32_t pack_bf162(float a, float b)
{
    __nv_bfloat162 t = __floats2bfloat162_rn(a, b);
    return *(uint32_t*)&t;
}

// cvt two fp32 -> bf16x2 (lo, hi), then exp2 both halves in ONE MUFU op.
__device__ __forceinline__ uint32_t ex2_pair(float lo, float hi)
{
    uint32_t t, y;
    asm("cvt.rn.bf16x2.f32 %0, %1, %2;\n" : "=r"(t) : "f"(hi), "f"(lo));
    asm("ex2.approx.ftz.bf16x2 %0, %1;\n" : "=r"(y) : "r"(t));
    return y;
}

__device__ __forceinline__ void cp_async16(void* smem_dst, const void* gmem_src)
{
    uint32_t d = (uint32_t)__cvta_generic_to_shared(smem_dst);
    asm volatile("cp.async.cg.shared.global [%0], [%1], 16;\n"
                 :: "r"(d), "l"(gmem_src) : "memory");
}
__device__ __forceinline__ void cp_async_commit()
{
    asm volatile("cp.async.commit_group;\n" ::: "memory");
}
__device__ __forceinline__ void cp_async_wait0()
{
    asm volatile("cp.async.wait_group 0;\n" ::: "memory");
}

// ---------------------------------------------------------------------------
// Kernel 1: projections as HMMA GEMM.  [64 rows x 64] @ [64 x 80] per block.
// 512 blocks x 128 threads (4 warps, 16 rows each), float4 weight staging.
// Wg pre-scaled by log2e.
// ---------------------------------------------------------------------------
#define LDW 88
#define LDX 72
__global__ __launch_bounds__(128) void proj_kernel(
    const float* __restrict__ x,
    const float* __restrict__ kf,
    const float* __restrict__ kg,
    const float* __restrict__ kh)
{
    __shared__ __nv_bfloat16 sW[64 * LDW];    // row c: d 0-7 f, 8-15 g(scaled), 16-79 h
    __shared__ __nv_bfloat16 sX[64 * LDX];

    int tid  = threadIdx.x;
    int lane = tid & 31;
    int w    = tid >> 5;
    int gid  = lane >> 2;
    int tg   = lane & 3;

    // Vectorized weight staging: flat float4 index over [kf | kg | kh].
    for (int i = tid; i < 1280; i += 128) {
        float4 v;
        int c, d;
        float sc = 1.f;
        if (i < 128) {
            v = ((const float4*)kf)[i];
            int e = i * 4;  c = e >> 3;  d = e & 7;
        } else if (i < 256) {
            v = ((const float4*)kg)[i - 128];
            int e = (i - 128) * 4;  c = e >> 3;  d = (e & 7) + 8;
            sc = LOG2E;
        } else {
            v = ((const float4*)kh)[i - 256];
            int e = (i - 256) * 4;  c = e >> 6;  d = (e & 63) + 16;
        }
        __nv_bfloat16* dst = &sW[c * LDW + d];
        dst[0] = __float2bfloat16(v.x * sc);
        dst[1] = __float2bfloat16(v.y * sc);
        dst[2] = __float2bfloat16(v.z * sc);
        dst[3] = __float2bfloat16(v.w * sc);
    }
    long base = (long)blockIdx.x * 64;
    const float4* xg = (const float4*)(x + base * 64);
    for (int i = tid; i < 1024; i += 128) {
        int r = i >> 4, c4 = (i & 15) * 4;
        float4 v = xg[i];
        __nv_bfloat162* dst = (__nv_bfloat162*)&sX[r * LDX + c4];
        dst[0] = __floats2bfloat162_rn(v.x, v.y);
        dst[1] = __floats2bfloat162_rn(v.z, v.w);
    }
    __syncthreads();

    float c[10][4];
#pragma unroll
    for (int n = 0; n < 10; n++)
#pragma unroll
        for (int i = 0; i < 4; i++) c[n][i] = 0.f;

#pragma unroll
    for (int kk = 0; kk < 4; kk++) {
        uint32_t a[4];
        ldsm_x4(a, &sX[(w * 16 + (lane & 15)) * LDX + kk * 16 + (lane >> 4) * 8]);
#pragma unroll
        for (int np = 0; np < 5; np++) {
            uint32_t bfr[4];
            ldsm_x4_trans(bfr,
                &sW[(kk * 16 + (lane & 15)) * LDW + np * 16 + (lane >> 4) * 8]);
            mma_16n8k16(c[2 * np],     a, &bfr[0]);
            mma_16n8k16(c[2 * np + 1], a, &bfr[2]);
        }
    }

    // Fragment-direct scattered stores: d = 16*np + 8*h + 2*tg (static routing).
    long r0 = base + w * 16 + gid;
    long r1 = r0 + 8;
#pragma unroll
    for (int np = 0; np < 5; np++) {
#pragma unroll
        for (int h = 0; h < 2; h++) {
            int dbase = 16 * np + 8 * h;
            uint32_t u0 = pack_bf162(c[2 * np + h][0], c[2 * np + h][1]);
            uint32_t u1 = pack_bf162(c[2 * np + h][2], c[2 * np + h][3]);
            if (dbase == 0) {
                *(uint32_t*)&g_f[r0 * QD + 2 * tg] = u0;
                *(uint32_t*)&g_f[r1 * QD + 2 * tg] = u1;
            } else if (dbase == 8) {
                *(uint32_t*)&g_g[r0 * QD + 2 * tg] = u0;
                *(uint32_t*)&g_g[r1 * QD + 2 * tg] = u1;
            } else {
                int d = dbase - 16 + 2 * tg;
                *(uint32_t*)&g_h[r0 * CC + d] = u0;
                *(uint32_t*)&g_h[r1 * CC + d] = u1;
            }
        }
    }
}

// ---------------------------------------------------------------------------
// Kernel 2: flash attention. 128 threads = 2 key-parity pairs (2 warps each).
// Pair p handles key tiles kt = p, p+2, ...; warp-in-pair wp covers rows
// [wp*32, wp*32+32) as two m16 chunks sharing every H B-fragment.
// S is software-pipelined one 16-key slab ahead so ex2/PV of slab kk hides
// the S-MMA latency of slab kk+1. Row-sums on the tensor pipe (ones column).
// Epilogue is symmetric: pair 0 finalizes rows 0-31, pair 1 rows 32-63.
// ---------------------------------------------------------------------------
__global__ __launch_bounds__(128, 3) void attn_kernel(
    const float* __restrict__ x,
    const float* __restrict__ gamma_p,
    float* __restrict__ out)
{
    __shared__ __nv_bfloat16 sG[BM * QD];             // 1 KB
    __shared__ __nv_bfloat16 sF[2][2][BN * QD];       // 4 KB   [pair][buf]
    __shared__ __nv_bfloat16 sH[2][2][BN * LDH];      // 36 KB  [pair][buf]
    __shared__ float         sL[BM];

    int tid  = threadIdx.x;
    int lane = tid & 31;
    int w    = tid >> 5;          // 0..3
    int pair = w >> 1;            // key-tile parity this warp handles
    int wp   = w & 1;             // warp-in-pair: row half
    int pt   = tid & 63;          // pair-local thread id
    int gid  = lane >> 2;
    int tg   = lane & 3;
    int b    = blockIdx.x / QT;
    int qt   = blockIdx.x % QT;
    long qbase = (long)b * NN + (long)qt * BM;
    long kb0   = (long)b * NN;

    float gmm = gamma_p[0];

    // Ones B-fragment for rowsum MMA: column n=0 of B[k,n] = 1.0 (bf16).
    uint32_t one2 = (lane < 4) ? 0x3F803F80u : 0u;
    uint32_t bones[2] = { one2, one2 };

    // Prologue: G tile + each pair's first key tile (kt = pair).
    if (tid < 64) cp_async16(&sG[tid * 8], &g_g[(qbase + tid) * QD]);
    {
        long kb = kb0 + (long)pair * BN;
        cp_async16(&sF[pair][0][pt * 8], &g_f[(kb + pt) * QD]);
#pragma unroll
        for (int i = 0; i < 8; i++) {
            int idx = pt + 64 * i;
            cp_async16(&sH[pair][0][(idx >> 3) * LDH + (idx & 7) * 8],
                       &g_h[kb * CC + idx * 8]);
        }
    }
    cp_async_commit();
    cp_async_wait0();
    __syncthreads();

    // G A-fragments for rows wp*32 + {gid, gid+8, gid+16, gid+24}.
    uint32_t ga0[2], ga1[2];
    ga0[0] = *(const uint32_t*)&sG[(wp * 32 + gid)      * QD + 2 * tg];
    ga0[1] = *(const uint32_t*)&sG[(wp * 32 + gid + 8)  * QD + 2 * tg];
    ga1[0] = *(const uint32_t*)&sG[(wp * 32 + gid + 16) * QD + 2 * tg];
    ga1[1] = *(const uint32_t*)&sG[(wp * 32 + gid + 24) * QD + 2 * tg];

    float o0[8][4], o1[8][4];
#pragma unroll
    for (int n = 0; n < 8; n++)
#pragma unroll
        for (int i = 0; i < 4; i++) { o0[n][i] = 0.f; o1[n][i] = 0.f; }
    float lacc0[4] = {0.f, 0.f, 0.f, 0.f};
    float lacc1[4] = {0.f, 0.f, 0.f, 0.f};

    const int NI = KT / 2;   // 32 iterations per pair
    for (int i = 0; i < NI; i++) {
        int buf = i & 1;
        const __nv_bfloat16* hb = &sH[pair][buf][0];

        // Prefetch this pair's next key tile (kt = 2*(i+1)+pair).
        if (i + 1 < NI) {
            long kb = kb0 + (long)(2 * (i + 1) + pair) * BN;
            cp_async16(&sF[pair][buf ^ 1][pt * 8], &g_f[(kb + pt) * QD]);
#pragma unroll
            for (int j = 0; j < 8; j++) {
                int idx = pt + 64 * j;
                cp_async16(&sH[pair][buf ^ 1][(idx >> 3) * LDH + (idx & 7) * 8],
                           &g_h[kb * CC + idx * 8]);
            }
            cp_async_commit();
        }

        // F B-fragments (single LDS.32 each).
        uint32_t fb[8];
#pragma unroll
        for (int j = 0; j < 8; j++)
            fb[j] = *(const uint32_t*)&sF[pair][buf][(j * 8 + gid) * QD + 2 * tg];

        // Software-pipelined slabs: S(kk+1) issued before ex2/PV of slab kk.
        float sA00[4], sA01[4], sA10[4], sA11[4];
#pragma unroll
        for (int v = 0; v < 4; v++) { sA00[v] = sA01[v] = sA10[v] = sA11[v] = 0.f; }
        mma_16n8k8(sA00, ga0, fb[0]);
        mma_16n8k8(sA01, ga0, fb[1]);
        mma_16n8k8(sA10, ga1, fb[0]);
        mma_16n8k8(sA11, ga1, fb[1]);

#pragma unroll
        for (int kk = 0; kk < 4; kk++) {
            float sB00[4], sB01[4], sB10[4], sB11[4];
            if (kk < 3) {
#pragma unroll
                for (int v = 0; v < 4; v++)
                    { sB00[v] = sB01[v] = sB10[v] = sB11[v] = 0.f; }
                mma_16n8k8(sB00, ga0, fb[2 * kk + 2]);
                mma_16n8k8(sB01, ga0, fb[2 * kk + 3]);
                mma_16n8k8(sB10, ga1, fb[2 * kk + 2]);
                mma_16n8k8(sB11, ga1, fb[2 * kk + 3]);
            }

            uint32_t a0[4], a1[4];
            a0[0] = ex2_pair(sA00[0], sA00[1]);
            a0[1] = ex2_pair(sA00[2], sA00[3]);
            a0[2] = ex2_pair(sA01[0], sA01[1]);
            a0[3] = ex2_pair(sA01[2], sA01[3]);
            a1[0] = ex2_pair(sA10[0], sA10[1]);
            a1[1] = ex2_pair(sA10[2], sA10[3]);
            a1[2] = ex2_pair(sA11[0], sA11[1]);
            a1[3] = ex2_pair(sA11[2], sA11[3]);

            // Row-sums on the tensor pipe (exact sum of the rounded P).
            mma_16n8k16(lacc0, a0, bones);
            mma_16n8k16(lacc1, a1, bones);

#pragma unroll
            for (int np = 0; np < 4; np++) {
                uint32_t bfr[4];
                ldsm_x4_trans(bfr,
                    &hb[(kk * 16 + (lane & 15)) * LDH + np * 16 + (lane >> 4) * 8]);
                mma_16n8k16(o0[2 * np],     a0, &bfr[0]);
                mma_16n8k16(o0[2 * np + 1], a0, &bfr[2]);
                mma_16n8k16(o1[2 * np],     a1, &bfr[0]);
                mma_16n8k16(o1[2 * np + 1], a1, &bfr[2]);
            }

            if (kk < 3) {
#pragma unroll
                for (int v = 0; v < 4; v++) {
                    sA00[v] = sB00[v]; sA01[v] = sB01[v];
                    sA10[v] = sB10[v]; sA11[v] = sB11[v];
                }
            }
        }

        if (i + 1 < NI) {
            cp_async_wait0();
            asm volatile("bar.sync %0, 64;\n" :: "r"(1 + pair) : "memory");
        }
    }

    // Row-sums live in column 0 of lacc (lanes with tg==0). Broadcast to the
    // 4 lanes of each row group.
    int src = lane & 28;
    float l0 = __shfl_sync(0xffffffffu, lacc0[0], src);
    float l1 = __shfl_sync(0xffffffffu, lacc0[2], src);
    float l2 = __shfl_sync(0xffffffffu, lacc1[0], src);
    float l3 = __shfl_sync(0xffffffffu, lacc1[2], src);

    // Symmetric epilogue: pair finalizes its rows [pair*32, pair*32+32); the
    // warp whose rows belong to the OTHER pair parks partials in smem.
    __syncthreads();
    float* sO = (float*)&sH[0][0][0];   // 64 x LDO floats (< 36 KB)
    int r0 = wp * 32 + gid;
    if (pair != wp) {
        // Park partial O + l for rows owned by the other pair's finalizer.
#pragma unroll
        for (int n = 0; n < 8; n++) {
            int col = n * 8 + 2 * tg;
            *(float2*)&sO[(r0)      * LDO + col] = make_float2(o0[n][0], o0[n][1]);
            *(float2*)&sO[(r0 + 8)  * LDO + col] = make_float2(o0[n][2], o0[n][3]);
            *(float2*)&sO[(r0 + 16) * LDO + col] = make_float2(o1[n][0], o1[n][1]);
            *(float2*)&sO[(r0 + 24) * LDO + col] = make_float2(o1[n][2], o1[n][3]);
        }
        if (tg == 0) {
            sL[r0] = l0; sL[r0 + 8] = l1; sL[r0 + 16] = l2; sL[r0 + 24] = l3;
        }
    }
    __syncthreads();
    if (pair == wp) {
        float inv0 = gmm / (l0 + sL[r0]);
        float inv1 = gmm / (l1 + sL[r0 + 8]);
        float inv2 = gmm / (l2 + sL[r0 + 16]);
        float inv3 = gmm / (l3 + sL[r0 + 24]);
        long rg = qbase + r0;
#pragma unroll
        for (int n = 0; n < 8; n++) {
            int col = n * 8 + 2 * tg;
            float2 p0 = *(const float2*)&sO[(r0)      * LDO + col];
            float2 p1 = *(const float2*)&sO[(r0 + 8)  * LDO + col];
            float2 p2 = *(const float2*)&sO[(r0 + 16) * LDO + col];
            float2 p3 = *(const float2*)&sO[(r0 + 24) * LDO + col];
            float2 x0 = *(const float2*)&x[(rg)      * CC + col];
            float2 x1 = *(const float2*)&x[(rg + 8)  * CC + col];
            float2 x2 = *(const float2*)&x[(rg + 16) * CC + col];
            float2 x3 = *(const float2*)&x[(rg + 24) * CC + col];
            float2 v;
            v.x = (o0[n][0] + p0.x) * inv0 + x0.x;
            v.y = (o0[n][1] + p0.y) * inv0 + x0.y;
            *(float2*)&out[(rg)      * CC + col] = v;
            v.x = (o0[n][2] + p1.x) * inv1 + x1.x;
            v.y = (o0[n][3] + p1.y) * inv1 + x1.y;
            *(float2*)&out[(rg + 8)  * CC + col] = v;
            v.x = (o1[n][0] + p2.x) * inv2 + x2.x;
            v.y = (o1[n][1] + p2.y) * inv2 + x2.y;
            *(float2*)&out[(rg + 16) * CC + col] = v;
            v.x = (o1[n][2] + p3.x) * inv3 + x3.x;
            v.y = (o1[n][3] + p3.y) * inv3 + x3.y;
            *(float2*)&out[(rg + 24) * CC + col] = v;
        }
    }
}

// ---------------------------------------------------------------------------

extern "C" void kernel_launch(void* const* d_in, const int* in_sizes, int n_in,
                              void* d_out, int out_size)
{
    const float* x     = (const float*)d_in[0];
    const float* kf    = (const float*)d_in[1];
    const float* kg    = (const float*)d_in[2];
    const float* kh    = (const float*)d_in[3];
    const float* gamma = (const float*)d_in[4];
    float*       out   = (float*)d_out;

    proj_kernel<<<(BB * NN) / 64, 128>>>(x, kf, kg, kh);
    attn_kernel<<<BB * QT, 128>>>(x, gamma, out);
}